// round 6
// baseline (speedup 1.0000x reference)
#include <cuda_runtime.h>
#include <math_constants.h>

// AutoCorrelation (Autoformer): q,k,v (32,8,2048,64) fp32.
// corr[r,d] = sum_j q[r,j]*k[r,(j-d)%64]; top-4 over d, softmax, gather v.
// out = [ V (B,H,L,E) | corr^T (B,E,H,L) ]
//
// One thread = one row. FFMA2 packs the reduction dim j into pairs.
//   even d=2s:   c2 += qE[m] (*) kE[(m-s)&31],  qE[m]=(q[2m],q[2m+1])
//   odd  d=2s+1: c2 += qO[m] (*) kE[(m-s)&31],  qO[m]=(q[2m+1],q[(2m+2)&63])
// Only kE[32] (64 regs) is array-resident; qE/qO are streamed from ONE smem
// tile per warp that is reused k -> q -> v. launch_bounds(64,8) caps 128 regs
// -> 16 warps/SM (occupancy was the R5 limiter).

#define FMA2(c, a, b) \
    asm("fma.rn.f32x2 %0, %1, %2, %0;" : "+l"(c) : "l"(a), "l"(b))
#define UNPACK2(lo, hi, d) \
    asm("mov.b64 {%0, %1}, %2;" : "=f"(lo), "=f"(hi) : "l"(d))
#define PACK2(d, lo, hi) \
    asm("mov.b64 %0, {%1, %2};" : "=l"(d) : "f"(lo), "f"(hi))

#define STR2 33   // float2 row stride (66 floats): LDS.64 at 2-phase floor

// topk insert, strict > keeps lowest index on ties (lax.top_k order)
#define TOPK_INS(vv, d)                                                          \
    if (vv > w3) {                                                               \
        if (vv > w2) {                                                           \
            if (vv > w1) {                                                       \
                if (vv > w0) { w3=w2;i3=i2; w2=w1;i2=i1; w1=w0;i1=i0; w0=vv;i0=d;}\
                else          { w3=w2;i3=i2; w2=w1;i2=i1; w1=vv;i1=d; }          \
            } else            { w3=w2;i3=i2; w2=vv;i2=d; }                       \
        } else                { w3=vv;i3=d; }                                    \
    }

__global__ void __launch_bounds__(64, 8)
autocorr_kernel(const float* __restrict__ gq,
                const float* __restrict__ gk,
                const float* __restrict__ gv,
                float* __restrict__ outV,
                float* __restrict__ outC) {
    __shared__ float2 tile[2][32][STR2];       // ONE tile per warp, reused k->q->v

    const int w    = threadIdx.x >> 5;
    const int lane = threadIdx.x & 31;
    float2 (*T2)[STR2] = tile[w];
    float*  Tf = (float*)&T2[0][0];

    const long long r0  = ((long long)blockIdx.x * 2 + w) * 32;  // 32 rows/warp
    const long long off = r0 * 64;

    // stage 32 rows x 64 floats (coalesced LDG; STS bank (2it+lane)%... 2-way max)
#define STAGE(gsrc)                                                          \
    _Pragma("unroll 16")                                                     \
    for (int it = 0; it < 64; it++) {                                        \
        Tf[(it >> 1) * (2 * STR2) + ((it & 1) << 5) + lane]                  \
            = gsrc[off + it * 32 + lane];                                    \
    }

    // ---- k: stage, pack aligned pairs kE[t]=(k[2t],k[2t+1]) into regs ----
    STAGE(gk);
    __syncwarp();
    unsigned long long kE[32];
    #pragma unroll
    for (int t = 0; t < 32; t++)
        kE[t] = *(const unsigned long long*)&T2[lane][t];
    __syncwarp();

    // ---- q into the same tile ----
    STAGE(gq);
    __syncwarp();

    // ---- top-4 state ----
    float w0=-CUDART_INF_F, w1=-CUDART_INF_F, w2=-CUDART_INF_F, w3=-CUDART_INF_F;
    int   i0=0, i1=0, i2=0, i3=0;

    // corr^T: rows of this warp share (b,h); l = l0 + lane
    const int b = (int)(r0 >> 14);
    const int h = ((int)(r0 >> 11)) & 7;
    const int l = ((int)(r0 & 2047)) + lane;
    float* cA = outC + (long long)b * (64 * 8 * 2048) + (long long)h * 2048 + l;

    // ---- EVEN d: 2 passes x 16 packed accumulators, aligned LDS.64 q ----
    #pragma unroll
    for (int p = 0; p < 2; p++) {
        unsigned long long c2[16];
        #pragma unroll
        for (int dd = 0; dd < 16; dd++) c2[dd] = 0ull;

        #pragma unroll
        for (int m = 0; m < 32; m++) {
            unsigned long long q2 = *(const unsigned long long*)&T2[lane][m];
            #pragma unroll
            for (int dd = 0; dd < 16; dd++)
                FMA2(c2[dd], q2, kE[(m + 32 - p * 16 - dd) & 31]);
        }
        #pragma unroll
        for (int dd = 0; dd < 16; dd++) {
            const int d = 2 * (p * 16 + dd);
            float lo, hi; UNPACK2(lo, hi, c2[dd]);
            const float v = lo + hi;
            cA[d * 16384] = v;
            TOPK_INS(v, d);
        }
    }

    // ---- ODD d: 2 passes, misaligned q pairs qO[m]=(q[2m+1],q[(2m+2)&63]) ----
    #pragma unroll
    for (int p = 0; p < 2; p++) {
        unsigned long long c2[16];
        #pragma unroll
        for (int dd = 0; dd < 16; dd++) c2[dd] = 0ull;

        #pragma unroll
        for (int m = 0; m < 32; m++) {
            unsigned long long q2;
            PACK2(q2, Tf[lane * (2 * STR2) + 2 * m + 1],
                      Tf[lane * (2 * STR2) + ((2 * m + 2) & 63)]);
            #pragma unroll
            for (int dd = 0; dd < 16; dd++)
                FMA2(c2[dd], q2, kE[(m + 32 - p * 16 - dd) & 31]);
        }
        #pragma unroll
        for (int dd = 0; dd < 16; dd++) {
            const int d = 2 * (p * 16 + dd) + 1;
            float lo, hi; UNPACK2(lo, hi, c2[dd]);
            const float v = lo + hi;
            cA[d * 16384] = v;
            TOPK_INS(v, d);
        }
    }

    // ---- softmax over the 4 weights (w0 is the max) ----
    const float e1 = __expf(w1 - w0), e2 = __expf(w2 - w0), e3 = __expf(w3 - w0);
    const float inv = 1.f / (1.f + e1 + e2 + e3);
    const float t0 = inv, t1 = e1 * inv, t2 = e2 * inv, t3 = e3 * inv;

    // ---- v into the same tile (q is dead) ----
    __syncwarp();
    STAGE(gv);
    __syncwarp();

    // ---- gather + direct V store (float4; L2 merges half-sectors) ----
    {
        const float* vp = Tf + lane * (2 * STR2);
        float* outR = outV + off + lane * 64;
        #pragma unroll
        for (int eg = 0; eg < 16; eg++) {
            float4 o;
            #pragma unroll
            for (int s = 0; s < 4; s++) {
                const int e = eg * 4 + s;
                float sa =      t0 * vp[(e + i0) & 63];
                sa = fmaf(t1, vp[(e + i1) & 63], sa);
                sa = fmaf(t2, vp[(e + i2) & 63], sa);
                sa = fmaf(t3, vp[(e + i3) & 63], sa);
                (&o.x)[s] = sa;
            }
            *(float4*)(outR + eg * 4) = o;
        }
    }
}

extern "C" void kernel_launch(void* const* d_in, const int* in_sizes, int n_in,
                              void* d_out, int out_size) {
    const float* q = (const float*)d_in[0];
    const float* k = (const float*)d_in[1];
    const float* v = (const float*)d_in[2];
    float* outV = (float*)d_out;
    float* outC = (float*)d_out + (long long)32 * 8 * 2048 * 64;

    const int rows    = 32 * 8 * 2048;      // 524288
    const int nblocks = rows / 64;          // 8192 blocks, 2 warps (64 rows) each
    autocorr_kernel<<<nblocks, 64>>>(q, k, v, outV, outC);
}

// round 7
// speedup vs baseline: 1.5075x; 1.5075x over previous
#include <cuda_runtime.h>
#include <math_constants.h>

// AutoCorrelation (Autoformer): q,k,v (32,8,2048,64) fp32.
// corr[r,d] = sum_j q[r,j]*k[r,(j-d)%64]; top-4 over d, softmax, gather v.
// out = [ V (B,H,L,E) | corr^T (B,E,H,L) ]
//
// One thread = one row, ALL SCALAR (FFMA2 abandoned: every packed layout
// needs >=160 regs -> spills or 12-warp occupancy; R3/R4/R6 evidence).
// k resident in 64 regs; q streamed from a stride-67 smem tile (conflict-
// free); 4 passes x 16 accumulators keep live regs ~115 so the kernel fits
// the launch_bounds(64,8) 128-reg cap -> 16 warps/SM (25% occ vs R2's 18%).

#define STRS 67   // odd stride: bank (3*lane + j) % 32 distinct per lane

// topk insert, strict > keeps lowest index on ties (lax.top_k order)
#define TOPK_INS(vv, d)                                                          \
    if (vv > w3) {                                                               \
        if (vv > w2) {                                                           \
            if (vv > w1) {                                                       \
                if (vv > w0) { w3=w2;i3=i2; w2=w1;i2=i1; w1=w0;i1=i0; w0=vv;i0=d;}\
                else          { w3=w2;i3=i2; w2=w1;i2=i1; w1=vv;i1=d; }          \
            } else            { w3=w2;i3=i2; w2=vv;i2=d; }                       \
        } else                { w3=vv;i3=d; }                                    \
    }

__global__ void __launch_bounds__(64, 8)
autocorr_kernel(const float* __restrict__ gq,
                const float* __restrict__ gk,
                const float* __restrict__ gv,
                float* __restrict__ outV,
                float* __restrict__ outC) {
    __shared__ float tile[2][32][STRS];        // one tile per warp, reused k->q->v

    const int w    = threadIdx.x >> 5;
    const int lane = threadIdx.x & 31;
    float* Tf = &tile[w][0][0];

    const long long r0  = ((long long)blockIdx.x * 2 + w) * 32;  // 32 rows/warp
    const long long off = r0 * 64;

    // stage 32 rows x 64 floats: coalesced LDG, conflict-free STS
#define STAGE(gsrc)                                                          \
    _Pragma("unroll 8")                                                      \
    for (int it = 0; it < 64; it++) {                                        \
        Tf[(it >> 1) * STRS + ((it & 1) << 5) + lane]                        \
            = gsrc[off + it * 32 + lane];                                    \
    }

    // ---- k: stage, pull row into 64 regs ----
    STAGE(gk);
    __syncwarp();
    float kr[64];
    #pragma unroll
    for (int j = 0; j < 64; j++) kr[j] = Tf[lane * STRS + j];
    __syncwarp();

    // ---- q into the same tile ----
    STAGE(gq);
    __syncwarp();

    // ---- top-4 state ----
    float w0=-CUDART_INF_F, w1=-CUDART_INF_F, w2=-CUDART_INF_F, w3=-CUDART_INF_F;
    int   i0=0, i1=0, i2=0, i3=0;

    // corr^T: rows of this warp share (b,h); l = l0 + lane
    const int b = (int)(r0 >> 14);
    const int h = ((int)(r0 >> 11)) & 7;
    const int l = ((int)(r0 & 2047)) + lane;
    float* cA = outC + (long long)b * (64 * 8 * 2048) + (long long)h * 2048 + l;

    // ---- correlation: 4 passes x 16 accumulators, fully unrolled ----
    #pragma unroll
    for (int p = 0; p < 4; p++) {
        float c[16];
        #pragma unroll
        for (int dd = 0; dd < 16; dd++) c[dd] = 0.f;

        #pragma unroll
        for (int j = 0; j < 64; j++) {
            const float qj = Tf[lane * STRS + j];   // 1-phase LDS, reused x16
            #pragma unroll
            for (int dd = 0; dd < 16; dd++)
                c[dd] = fmaf(qj, kr[(j + 64 - p * 16 - dd) & 63], c[dd]);
        }

        #pragma unroll
        for (int dd = 0; dd < 16; dd++) {
            const int d = p * 16 + dd;
            const float v = c[dd];
            cA[d * 16384] = v;                      // lanes contiguous in l
            TOPK_INS(v, d);
        }
    }

    // ---- softmax over the 4 weights (w0 is the max) ----
    const float e1 = __expf(w1 - w0), e2 = __expf(w2 - w0), e3 = __expf(w3 - w0);
    const float inv = 1.f / (1.f + e1 + e2 + e3);
    const float t0 = inv, t1 = e1 * inv, t2 = e2 * inv, t3 = e3 * inv;

    // ---- v into the same tile (q dead) ----
    __syncwarp();
    STAGE(gv);
    __syncwarp();

    // ---- gather + direct V store (float4 groups; L2 merges half-sectors) ----
    {
        const float* vp = Tf + lane * STRS;
        float* outR = outV + off + lane * 64;
        #pragma unroll
        for (int eg = 0; eg < 16; eg++) {
            float4 o;
            #pragma unroll
            for (int s = 0; s < 4; s++) {
                const int e = eg * 4 + s;
                float sa =      t0 * vp[(e + i0) & 63];
                sa = fmaf(t1, vp[(e + i1) & 63], sa);
                sa = fmaf(t2, vp[(e + i2) & 63], sa);
                sa = fmaf(t3, vp[(e + i3) & 63], sa);
                (&o.x)[s] = sa;
            }
            *(float4*)(outR + eg * 4) = o;
        }
    }
}

extern "C" void kernel_launch(void* const* d_in, const int* in_sizes, int n_in,
                              void* d_out, int out_size) {
    const float* q = (const float*)d_in[0];
    const float* k = (const float*)d_in[1];
    const float* v = (const float*)d_in[2];
    float* outV = (float*)d_out;
    float* outC = (float*)d_out + (long long)32 * 8 * 2048 * 64;

    const int rows    = 32 * 8 * 2048;      // 524288
    const int nblocks = rows / 64;          // 8192 blocks, 2 warps (64 rows) each
    autocorr_kernel<<<nblocks, 64>>>(q, k, v, outV, outC);
}

// round 8
// speedup vs baseline: 2.8506x; 1.8910x over previous
#include <cuda_runtime.h>
#include <math_constants.h>

// AutoCorrelation (Autoformer): q,k,v (32,8,2048,64) fp32.
// corr[r,d] = sum_j q[r,j]*k[r,(j-d)%64]; top-4 over d, softmax, gather v.
// out = [ V (B,H,L,E) | corr^T (B,E,H,L) ]
//
// R2 structure (one thread = one row, kr[64] resident, 2 passes x 32 accs,
// 168 regs / 12 warps/SM — the proven no-spill floor) + cp.async pipelining:
// LDGSTS has no register cost, so k,q prefetch overlap each other and the
// v prefetch hides its whole DRAM latency behind the ~4300-cyc corr phase.

#define STRS 65   // odd float stride: row-scalar access bank (r+j)%32, conflict-free

#define CP_ASYNC4(smem_u32, gptr) \
    asm volatile("cp.async.ca.shared.global [%0], [%1], 4;" \
                 :: "r"(smem_u32), "l"(gptr) : "memory")
#define CP_COMMIT()  asm volatile("cp.async.commit_group;" ::: "memory")
#define CP_WAIT(N)   asm volatile("cp.async.wait_group %0;" :: "n"(N) : "memory")

// topk insert, strict > keeps lowest index on ties (lax.top_k order)
#define TOPK_INS(vv, d)                                                          \
    if (vv > w3) {                                                               \
        if (vv > w2) {                                                           \
            if (vv > w1) {                                                       \
                if (vv > w0) { w3=w2;i3=i2; w2=w1;i2=i1; w1=w0;i1=i0; w0=vv;i0=d;}\
                else          { w3=w2;i3=i2; w2=w1;i2=i1; w1=vv;i1=d; }          \
            } else            { w3=w2;i3=i2; w2=vv;i2=d; }                       \
        } else                { w3=vv;i3=d; }                                    \
    }

__global__ void __launch_bounds__(64, 6)
autocorr_kernel(const float* __restrict__ gq,
                const float* __restrict__ gk,
                const float* __restrict__ gv,
                float* __restrict__ outV,
                float* __restrict__ outC) {
    __shared__ float tq [2][32][STRS];   // q tile per warp
    __shared__ float tkv[2][32][STRS];   // k tile, reused for v after kr pull

    const int w    = threadIdx.x >> 5;
    const int lane = threadIdx.x & 31;
    float* Q = &tq [w][0][0];
    float* K = &tkv[w][0][0];
    const unsigned Qs = (unsigned)__cvta_generic_to_shared(Q);
    const unsigned Ks = (unsigned)__cvta_generic_to_shared(K);

    const long long r0  = ((long long)blockIdx.x * 2 + w) * 32;  // 32 rows/warp
    const long long off = r0 * 64;

    // async-stage 32 rows x 64 floats (coalesced gmem, conflict-free smem)
#define ASTAGE(smem_base_u32, gsrc)                                          \
    _Pragma("unroll")                                                        \
    for (int it = 0; it < 64; it++) {                                        \
        const int fi = (it >> 1) * STRS + ((it & 1) << 5) + lane;            \
        CP_ASYNC4(smem_base_u32 + 4u * fi, gsrc + off + it * 32 + lane);     \
    }

    // ---- issue k then q prefetch; groups retire in order ----
    ASTAGE(Ks, gk); CP_COMMIT();     // group: k
    ASTAGE(Qs, gq); CP_COMMIT();     // group: q

    // ---- k ready -> pull row into 64 regs ----
    CP_WAIT(1);                      // <=1 outstanding: k done
    __syncwarp();
    float kr[64];
    #pragma unroll
    for (int j = 0; j < 64; j++) kr[j] = K[lane * STRS + j];
    __syncwarp();

    // ---- v prefetch into the k tile; hides behind the whole corr phase ----
    ASTAGE(Ks, gv); CP_COMMIT();     // group: v

    CP_WAIT(1);                      // <=1 outstanding: q done (v may fly)
    __syncwarp();

    // ---- top-4 state ----
    float w0=-CUDART_INF_F, w1=-CUDART_INF_F, w2=-CUDART_INF_F, w3=-CUDART_INF_F;
    int   i0=0, i1=0, i2=0, i3=0;

    // corr^T: rows of this warp share (b,h); l = l0 + lane
    const int b = (int)(r0 >> 14);
    const int h = ((int)(r0 >> 11)) & 7;
    const int l = ((int)(r0 & 2047)) + lane;
    float* cA = outC + (long long)b * (64 * 8 * 2048) + (long long)h * 2048 + l;

    // ---- correlation: 2 passes x 32 accumulators (R2 proven layout) ----
    #pragma unroll
    for (int p = 0; p < 2; p++) {
        float c[32];
        #pragma unroll
        for (int dd = 0; dd < 32; dd++) c[dd] = 0.f;

        #pragma unroll
        for (int j = 0; j < 64; j++) {
            const float qj = Q[lane * STRS + j];    // 1-phase LDS, reused x32
            #pragma unroll
            for (int dd = 0; dd < 32; dd++)
                c[dd] = fmaf(qj, kr[(j + 64 - p * 32 - dd) & 63], c[dd]);
        }

        #pragma unroll
        for (int dd = 0; dd < 32; dd++) {
            const int d = p * 32 + dd;
            const float v = c[dd];
            cA[d * 16384] = v;                      // lanes contiguous in l
            TOPK_INS(v, d);
        }
    }

    // ---- softmax over the 4 weights (w0 is the max) ----
    const float e1 = __expf(w1 - w0), e2 = __expf(w2 - w0), e3 = __expf(w3 - w0);
    const float inv = 1.f / (1.f + e1 + e2 + e3);
    const float t0 = inv, t1 = e1 * inv, t2 = e2 * inv, t3 = e3 * inv;

    // ---- v already resident (prefetched behind corr) ----
    CP_WAIT(0);
    __syncwarp();

    // ---- gather + direct V store (float4; L2 merges half-sectors) ----
    {
        const float* vp = K + lane * STRS;
        float* outR = outV + off + lane * 64;
        #pragma unroll
        for (int eg = 0; eg < 16; eg++) {
            float4 o;
            #pragma unroll
            for (int s = 0; s < 4; s++) {
                const int e = eg * 4 + s;
                float sa =      t0 * vp[(e + i0) & 63];
                sa = fmaf(t1, vp[(e + i1) & 63], sa);
                sa = fmaf(t2, vp[(e + i2) & 63], sa);
                sa = fmaf(t3, vp[(e + i3) & 63], sa);
                (&o.x)[s] = sa;
            }
            *(float4*)(outR + eg * 4) = o;
        }
    }
}

extern "C" void kernel_launch(void* const* d_in, const int* in_sizes, int n_in,
                              void* d_out, int out_size) {
    const float* q = (const float*)d_in[0];
    const float* k = (const float*)d_in[1];
    const float* v = (const float*)d_in[2];
    float* outV = (float*)d_out;
    float* outC = (float*)d_out + (long long)32 * 8 * 2048 * 64;

    const int rows    = 32 * 8 * 2048;      // 524288
    const int nblocks = rows / 64;          // 8192 blocks, 2 warps (64 rows) each
    autocorr_kernel<<<nblocks, 64>>>(q, k, v, outV, outC);
}